// round 6
// baseline (speedup 1.0000x reference)
#include <cuda_runtime.h>

// out[i] = (a^2 - 2*pi^2) * __sinf(pi*x0) * __sinf(pi*x1)   (P=1)
// N = 16777216 rows; input [N,2] fp32; out [N,1] fp32. Pure stream: 128MB R + 64MB W.
// Each thread: 16 rows = 8 independent LDG.128 (MLP=8, streaming) -> 4 STG.128.
// __sinf = MUFU.SIN keeps issue pressure trivial; goal is DRAM saturation.

__global__ void __launch_bounds__(256)
helm_kernel(const float4* __restrict__ in,
            const float*  __restrict__ a,
            float4* __restrict__ out,
            int n_chunks)   // number of 16-row chunks
{
    const float pi = 3.14159265358979323846f;
    int i = blockIdx.x * blockDim.x + threadIdx.x;
    if (i >= n_chunks) return;

    float av = a[0];                       // broadcast, L1-resident

    // Eight independent 16B streaming loads, front-batched (MLP=8)
    float4 v[8];
#pragma unroll
    for (int j = 0; j < 8; j++)
        v[j] = __ldcs(in + 8 * i + j);

    float coef = fmaf(av, av, -2.0f * pi * pi);

#pragma unroll
    for (int j = 0; j < 4; j++) {
        float4 r;
        r.x = coef * (__sinf(pi * v[2*j].x)   * __sinf(pi * v[2*j].y));
        r.y = coef * (__sinf(pi * v[2*j].z)   * __sinf(pi * v[2*j].w));
        r.z = coef * (__sinf(pi * v[2*j+1].x) * __sinf(pi * v[2*j+1].y));
        r.w = coef * (__sinf(pi * v[2*j+1].z) * __sinf(pi * v[2*j+1].w));
        __stcs(out + 4 * i + j, r);
    }
}

extern "C" void kernel_launch(void* const* d_in, const int* in_sizes, int n_in,
                              void* d_out, int out_size)
{
    const float4* in = (const float4*)d_in[0];   // [N,2] fp32
    const float*  a  = (const float*)d_in[1];    // [1] fp32
    float4* out = (float4*)d_out;                // [N] fp32

    int n_rows = out_size;          // N = 16777216 (divisible by 16)
    int n_chunks = n_rows / 16;     // 16 rows per thread -> 1,048,576 threads

    int block = 256;
    int grid = (n_chunks + block - 1) / block;   // 4096 blocks
    helm_kernel<<<grid, block>>>(in, a, out, n_chunks);
}

// round 8
// speedup vs baseline: 2.0811x; 2.0811x over previous
#include <cuda_runtime.h>

// out[i] = (a^2 - 2*pi^2) * __sinf(pi*x0) * __sinf(pi*x1)   (P=1)
// N = 16777216 rows; input [N,2] fp32; out [N,1] fp32. Pure stream: 128MB R + 64MB W.
// R5 structure (MLP=4, no spill, 33.2us) + streaming cache hints (.cs) on both
// loads and stores. NOTE: 8 live float4 spilled to local in R6 (regs=34, L1 87%);
// 4 live float4 is the proven no-spill budget.

__global__ void __launch_bounds__(256)
helm_kernel(const float4* __restrict__ in,
            const float*  __restrict__ a,
            float4* __restrict__ out,
            int n_chunks)   // number of 8-row chunks
{
    const float pi = 3.14159265358979323846f;
    int i = blockIdx.x * blockDim.x + threadIdx.x;
    if (i >= n_chunks) return;

    float av = a[0];                       // broadcast, L1-resident

    // Four independent 16B streaming loads, front-batched (MLP=4)
    float4 v0 = __ldcs(in + 4 * i + 0);
    float4 v1 = __ldcs(in + 4 * i + 1);
    float4 v2 = __ldcs(in + 4 * i + 2);
    float4 v3 = __ldcs(in + 4 * i + 3);

    float coef = fmaf(av, av, -2.0f * pi * pi);

    float4 r0, r1;
    r0.x = coef * (__sinf(pi * v0.x) * __sinf(pi * v0.y));
    r0.y = coef * (__sinf(pi * v0.z) * __sinf(pi * v0.w));
    r0.z = coef * (__sinf(pi * v1.x) * __sinf(pi * v1.y));
    r0.w = coef * (__sinf(pi * v1.z) * __sinf(pi * v1.w));
    r1.x = coef * (__sinf(pi * v2.x) * __sinf(pi * v2.y));
    r1.y = coef * (__sinf(pi * v2.z) * __sinf(pi * v2.w));
    r1.z = coef * (__sinf(pi * v3.x) * __sinf(pi * v3.y));
    r1.w = coef * (__sinf(pi * v3.z) * __sinf(pi * v3.w));

    __stcs(out + 2 * i + 0, r0);
    __stcs(out + 2 * i + 1, r1);
}

extern "C" void kernel_launch(void* const* d_in, const int* in_sizes, int n_in,
                              void* d_out, int out_size)
{
    const float4* in = (const float4*)d_in[0];   // [N,2] fp32
    const float*  a  = (const float*)d_in[1];    // [1] fp32
    float4* out = (float4*)d_out;                // [N] fp32

    int n_rows = out_size;          // N = 16777216 (divisible by 8)
    int n_chunks = n_rows / 8;      // 8 rows per thread

    int block = 256;
    int grid = (n_chunks + block - 1) / block;   // 8192 blocks
    helm_kernel<<<grid, block>>>(in, a, out, n_chunks);
}

// round 9
// speedup vs baseline: 2.1278x; 1.0224x over previous
#include <cuda_runtime.h>

// out[i] = (a^2 - 2*pi^2) * __sinf(pi*x0) * __sinf(pi*x1)   (P=1)
// N = 16777216 rows; input [N,2] fp32; out [N,1] fp32. Pure stream: 128MB R + 64MB W.
//
// Persistent grid-stride kernel, 2-stage software pipeline: batch k+1's four
// LDG.128 issue BEFORE batch k's compute+store, so every warp keeps >=4 loads
// in flight continuously. 8 live float4 at the overlap point -> force 64-reg
// budget via __launch_bounds__(256,4) to avoid the R6 spill (regs=34 -> local).
// Single wave: grid = 148 SMs * 4 CTAs = 592 blocks, no wave transitions.

__global__ void __launch_bounds__(256, 4)
helm_kernel(const float4* __restrict__ in,
            const float*  __restrict__ a,
            float4* __restrict__ out,
            int n_chunks)   // number of 8-row chunks
{
    const float pi = 3.14159265358979323846f;
    const int stride = gridDim.x * blockDim.x;
    int i = blockIdx.x * blockDim.x + threadIdx.x;

    float av = a[0];                         // broadcast, L1-resident
    float coef = fmaf(av, av, -2.0f * pi * pi);

    if (i >= n_chunks) return;

    // Prologue: load first batch (MLP=4)
    float4 v0 = __ldcs(in + 4 * i + 0);
    float4 v1 = __ldcs(in + 4 * i + 1);
    float4 v2 = __ldcs(in + 4 * i + 2);
    float4 v3 = __ldcs(in + 4 * i + 3);

    for (;;) {
        int inext = i + stride;
        bool more = inext < n_chunks;

        // Prefetch next batch BEFORE computing current (keeps DRAM pipe full)
        float4 w0, w1, w2, w3;
        if (more) {
            w0 = __ldcs(in + 4 * inext + 0);
            w1 = __ldcs(in + 4 * inext + 1);
            w2 = __ldcs(in + 4 * inext + 2);
            w3 = __ldcs(in + 4 * inext + 3);
        }

        // Compute + store current batch
        float4 r0, r1;
        r0.x = coef * (__sinf(pi * v0.x) * __sinf(pi * v0.y));
        r0.y = coef * (__sinf(pi * v0.z) * __sinf(pi * v0.w));
        r0.z = coef * (__sinf(pi * v1.x) * __sinf(pi * v1.y));
        r0.w = coef * (__sinf(pi * v1.z) * __sinf(pi * v1.w));
        r1.x = coef * (__sinf(pi * v2.x) * __sinf(pi * v2.y));
        r1.y = coef * (__sinf(pi * v2.z) * __sinf(pi * v2.w));
        r1.z = coef * (__sinf(pi * v3.x) * __sinf(pi * v3.y));
        r1.w = coef * (__sinf(pi * v3.z) * __sinf(pi * v3.w));
        __stcs(out + 2 * i + 0, r0);
        __stcs(out + 2 * i + 1, r1);

        if (!more) break;
        v0 = w0; v1 = w1; v2 = w2; v3 = w3;
        i = inext;
    }
}

extern "C" void kernel_launch(void* const* d_in, const int* in_sizes, int n_in,
                              void* d_out, int out_size)
{
    const float4* in = (const float4*)d_in[0];   // [N,2] fp32
    const float*  a  = (const float*)d_in[1];    // [1] fp32
    float4* out = (float4*)d_out;                // [N] fp32

    int n_rows = out_size;          // N = 16777216 (divisible by 8)
    int n_chunks = n_rows / 8;      // 8 rows per thread-iteration

    int block = 256;
    int grid = 148 * 4;             // persistent single wave, 4 CTAs/SM
    helm_kernel<<<grid, block>>>(in, a, out, n_chunks);
}